// round 8
// baseline (speedup 1.0000x reference)
#include <cuda_runtime.h>
#include <cstdint>

#define BB 64
#define SS 512
#define HH 768
#define KK 21
#define FULLMASK 0xffffffffu
#define LOG21 3.0445224377234229f

// ---------------------------------------------------------------------------
// helpers
// ---------------------------------------------------------------------------
__device__ __forceinline__ void fma2(unsigned long long& acc,
                                     unsigned long long a,
                                     unsigned long long b) {
    asm("fma.rn.f32x2 %0, %1, %2, %0;" : "+l"(acc) : "l"(a), "l"(b));
}
__device__ __forceinline__ float2 unpack2(unsigned long long v) {
    float lo, hi;
    asm("mov.b64 {%0,%1}, %2;" : "=f"(lo), "=f"(hi) : "l"(v));
    return make_float2(lo, hi);
}
__device__ __forceinline__ float rcpa(float x) {
    float r;
    asm("rcp.approx.f32 %0, %1;" : "=f"(r) : "f"(x));
    return r;
}
__device__ __forceinline__ void cpa8(void* dst, const void* src) {
    uint32_t d = (uint32_t)__cvta_generic_to_shared(dst);
    asm volatile("cp.async.ca.shared.global [%0], [%1], 8;\n" ::"r"(d), "l"(src));
}
__device__ __forceinline__ void cpa16(void* dst, const void* src) {
    uint32_t d = (uint32_t)__cvta_generic_to_shared(dst);
    asm volatile("cp.async.cg.shared.global [%0], [%1], 16;\n" ::"r"(d), "l"(src));
}

__device__ float4 g_wpack[384 * 11];
__device__ float  g_partial[BB];
__device__ int    g_ctr = 0;
__device__ int    g_packflag = 0;          // set-once (g_wpack replay-invariant)
__device__ int    g_tflag[256];            // per-tile flags (consumer-reset)

__device__ __forceinline__ void wait_flag(volatile int* f) {
    while (*f == 0) __nanosleep(64);
}

// ---------------------------------------------------------------------------
// config: 256 tiles of 128 rows; 128 worker blocks x 2 tiles; GT=256 threads
// ---------------------------------------------------------------------------
#define GT    256
#define GR    128
#define GSTR  66
#define WCH   352
#define NCH   12
#define HFLOATS (GR * GSTR)                 // 8448
#define GSMEM (2 * HFLOATS * 4 + 2 * WCH * 16)   // 78848 B

#define PACKB   BB          // block 64: pack W
#define GEMMB0  (BB + 1)    // blocks 65..192: gemm workers
#define NWORK   128
#define GRID    (GEMMB0 + NWORK)            // 193

// ---------------------------------------------------------------------------
// CRF primitives
// ---------------------------------------------------------------------------
#define RN 16

__device__ __forceinline__ int seq_len_w(const void* maskraw, int b, int lane) {
    const int* im = (const int*)maskraw;
    bool bytes = (im[0] != 1);
    int len = 0;
    if (!bytes) {
        const int* m = im + b * SS;
        for (int t = lane; t < SS; t += 32) len += (m[t] != 0);
    } else {
        const unsigned char* m = (const unsigned char*)maskraw + b * SS;
        for (int t = lane; t < SS; t += 32) len += (m[t] != 0);
    }
#pragma unroll
    for (int o = 16; o; o >>= 1) len += __shfl_xor_sync(FULLMASK, len, o);
    return len;
}

__device__ __forceinline__ float crf_step(float u, const float* tE, float e0) {
    float s[7];
#pragma unroll
    for (int i = 0; i < 7; i++) {
        float u0 = __shfl_sync(FULLMASK, u, 3 * i);
        float u1 = __shfl_sync(FULLMASK, u, 3 * i + 1);
        float u2 = __shfl_sync(FULLMASK, u, 3 * i + 2);
        float p = u0 * tE[3 * i];
        p = fmaf(u1, tE[3 * i + 1], p);
        p = fmaf(u2, tE[3 * i + 2], p);
        s[i] = p;
    }
    return (((s[0] + s[1]) + (s[2] + s[3])) + ((s[4] + s[5]) + s[6])) * e0;
}

__device__ __forceinline__ float crf_run(float u, float& logC, const float* tE,
                                         const float* lg, int jj,
                                         int base, int dir, int n) {
    if (n <= 0) return u;
    float ev[RN], evn[RN];
#pragma unroll
    for (int j = 0; j < RN; j++) {
        int idx = (j < n) ? j : n - 1;
        ev[j] = lg[(base + dir * idx) * KK + jj];
    }
    int pos = 0;
    while (pos + RN <= n) {
#pragma unroll
        for (int j = 0; j < RN; j++) {
            int idx = pos + RN + j; idx = (idx < n) ? idx : n - 1;
            evn[j] = lg[(base + dir * idx) * KK + jj];
        }
        float e0 = __expf(ev[0]);
#pragma unroll
        for (int j = 0; j < RN; j++) {
            float e1 = __expf(ev[(j + 1) & (RN - 1)]);
            u = crf_step(u, tE, e0);
            e0 = e1;
        }
        float c = __shfl_sync(FULLMASK, u, 0);
        u *= rcpa(c);
        logC += __logf(c);
#pragma unroll
        for (int j = 0; j < RN; j++) ev[j] = evn[j];
        pos += RN;
    }
    int tail = n - pos;
    for (int j = 0; j < tail; j++) {
        float e0 = __expf(ev[j]);
        u = crf_step(u, tE, e0);
    }
    if (tail) {
        float c = __shfl_sync(FULLMASK, u, 0);
        u *= rcpa(c);
        logC += __logf(c);
    }
    logC += (float)n * LOG21;
    return u;
}

// ---------------------------------------------------------------------------
// fused kernel
// ---------------------------------------------------------------------------
__global__ __launch_bounds__(GT, 2) void fused_kernel(
    const float* __restrict__ hidden,
    const float* __restrict__ Wg,
    const float* __restrict__ bg,
    const float* __restrict__ start_t,
    const float* __restrict__ trans,
    const float* __restrict__ end_t,
    const int*   __restrict__ labels,
    const void*  __restrict__ maskraw,
    float* __restrict__ out,
    float* __restrict__ out_nll) {
    extern __shared__ float dsm[];
    const int tid = threadIdx.x;
    const int bx = blockIdx.x;

    // ======================= PACK block =======================
    if (bx == PACKB) {
        for (int idx = tid; idx < 384 * 11; idx += GT) {
            int p = idx / 11, cc = idx - p * 11;
            int c0 = 2 * cc, c1 = c0 + 1;
            float a = Wg[(2 * p)     * KK + c0];
            float b = Wg[(2 * p + 1) * KK + c0];
            float c = (c1 < KK) ? Wg[(2 * p)     * KK + c1] : 0.f;
            float d = (c1 < KK) ? Wg[(2 * p + 1) * KK + c1] : 0.f;
            g_wpack[idx] = make_float4(a, b, c, d);
        }
        __threadfence();
        __syncthreads();
        if (tid == 0) atomicExch(&g_packflag, 1);
        return;
    }

    // ======================= GEMM worker blocks =======================
    if (bx >= GEMMB0) {
        const int wkr = bx - GEMMB0;          // 0..127
        float*  shh = dsm;
        float4* wb  = (float4*)(dsm + 2 * HFLOATS);
        const int r2 = tid & 63;              // rows r2 and r2+64
        const int h = tid >> 6;               // k-quarter (16 floats)

        wait_flag(&g_packflag);
        __threadfence();

        for (int tt = 0; tt < 2; tt++) {
            const int g = wkr + tt * NWORK;   // tile 0..255
            const size_t rowBase = (size_t)g * GR;

            auto LOADC = [&](int c, int buf) {
                const float* hsrc = hidden + rowBase * HH + c * 64;
                float* dst = shh + buf * HFLOATS;
#pragma unroll
                for (int j = 0; j < 16; j++) {
                    int idx = tid + j * GT;   // 4096 8B units
                    int row = idx >> 5, u8 = idx & 31;
                    cpa8(&dst[row * GSTR + u8 * 2],
                         hsrc + (size_t)row * HH + u8 * 2);
                }
                if (tid < WCH - GT)
                    cpa16(&wb[buf * WCH + GT + tid], &g_wpack[c * WCH + GT + tid]);
                cpa16(&wb[buf * WCH + tid], &g_wpack[c * WCH + tid]);
                asm volatile("cp.async.commit_group;\n");
            };

            unsigned long long accA[KK], accB[KK];
#pragma unroll
            for (int i = 0; i < KK; i++) { accA[i] = 0ull; accB[i] = 0ull; }

            LOADC(0, 0);
            for (int c = 0; c < NCH; c++) {
                if (c + 1 < NCH) {
                    LOADC(c + 1, (c + 1) & 1);
                    asm volatile("cp.async.wait_group 1;\n");
                } else {
                    asm volatile("cp.async.wait_group 0;\n");
                }
                __syncthreads();

                const float* hpA =
                    &shh[(c & 1) * HFLOATS + r2 * GSTR + h * 16];
                const float* hpB = hpA + 64 * GSTR;
                const float4* wp = &wb[(c & 1) * WCH + (h * 8) * 11];
#pragma unroll
                for (int p = 0; p < 8; p++) {
                    unsigned long long h2a =
                        *(const unsigned long long*)&hpA[2 * p];
                    unsigned long long h2b =
                        *(const unsigned long long*)&hpB[2 * p];
                    const ulonglong2* wrow = (const ulonglong2*)&wp[p * 11];
#pragma unroll
                    for (int cc = 0; cc < 10; cc++) {
                        ulonglong2 w2 = wrow[cc];
                        fma2(accA[2 * cc],     h2a, w2.x);
                        fma2(accA[2 * cc + 1], h2a, w2.y);
                        fma2(accB[2 * cc],     h2b, w2.x);
                        fma2(accB[2 * cc + 1], h2b, w2.y);
                    }
                    ulonglong2 w2 = wrow[10];
                    fma2(accA[20], h2a, w2.x);
                    fma2(accB[20], h2b, w2.x);
                }
                __syncthreads();
            }

            // epilogue: combine 4 k-quarters via smem, add bias, store
            float resA[KK], resB[KK];
#pragma unroll
            for (int cc = 0; cc < KK; cc++) {
                float2 fa = unpack2(accA[cc]);
                float2 fb = unpack2(accB[cc]);
                resA[cc] = fa.x + fa.y;
                resB[cc] = fb.x + fb.y;
            }
            float* bufA = shh;                 // 128*22
            float* bufB = shh + GR * 22;       // 128*22
            float* shOut = shh + 2 * GR * 22;  // 128*21
            if (h == 1 || h == 3) {
                float* bf = (h == 1) ? bufA : bufB;
#pragma unroll
                for (int cc = 0; cc < KK; cc++) {
                    bf[r2 * 22 + cc] = resA[cc];
                    bf[(64 + r2) * 22 + cc] = resB[cc];
                }
            }
            __syncthreads();
            if (h == 0 || h == 2) {
                float* bf = (h == 0) ? bufA : bufB;
#pragma unroll
                for (int cc = 0; cc < KK; cc++) {
                    resA[cc] += bf[r2 * 22 + cc];
                    resB[cc] += bf[(64 + r2) * 22 + cc];
                }
            }
            __syncthreads();
            if (h == 2) {
#pragma unroll
                for (int cc = 0; cc < KK; cc++) {
                    bufA[r2 * 22 + cc] = resA[cc];
                    bufA[(64 + r2) * 22 + cc] = resB[cc];
                }
            }
            __syncthreads();
            if (h == 0) {
#pragma unroll
                for (int cc = 0; cc < KK; cc++) {
                    shOut[r2 * KK + cc] =
                        resA[cc] + bufA[r2 * 22 + cc] + bg[cc];
                    shOut[(64 + r2) * KK + cc] =
                        resB[cc] + bufA[(64 + r2) * 22 + cc] + bg[cc];
                }
            }
            __syncthreads();
            float* outp = out + rowBase * KK;
            for (int i = tid; i < GR * KK; i += GT) outp[i] = shOut[i];

            __threadfence();
            __syncthreads();
            if (tid == 0) atomicExch(&g_tflag[g], 1);
            __syncthreads();                   // smem safe for next tile
        }
        return;
    }

    // ======================= CRF blocks (bx = batch) =======================
    const int b = bx;
    const int lane = tid & 31;
    const int w = tid >> 5;
    const int jj = (lane < KK) ? lane : KK - 1;

    __shared__ float s_uf[32], s_ub[32];
    __shared__ float s_cf, s_cb, s_num, s_end;

    const int*   lab = labels + b * SS;
    const float* lg  = out + (size_t)b * SS * KK;

    if (w < 3) {
        const int len = seq_len_w(maskraw, b, lane);
        const int m = len >> 1;

        if (w == 0) {
            float tE[KK];
#pragma unroll
            for (int i = 0; i < KK; i++)
                tE[i] = __expf(trans[i * KK + jj]) * (1.f / 21.f);
            wait_flag(&g_tflag[4 * b]);
            __threadfence();
            float a0 = (lane < KK) ? (start_t[lane] + lg[lane]) : -1e30f;
            float m0 = a0;
#pragma unroll
            for (int o = 16; o; o >>= 1)
                m0 = fmaxf(m0, __shfl_xor_sync(FULLMASK, m0, o));
            float u = __expf(a0 - m0);
            float logC = m0;
            for (int k = 0; k < 4; k++) {
                int lo = 128 * k; if (lo < 1) lo = 1;
                int hi = 128 * k + 127; if (hi > m) hi = m;
                if (lo > hi) continue;
                if (k > 0) { wait_flag(&g_tflag[4 * b + k]); __threadfence(); }
                u = crf_run(u, logC, tE, lg, jj, lo, +1, hi - lo + 1);
            }
            s_uf[lane] = u;
            if (lane == 0) s_cf = logC;
        } else if (w == 1) {
            float tEb[KK];
#pragma unroll
            for (int i = 0; i < KK; i++)
                tEb[i] = __expf(trans[jj * KK + i]) * (1.f / 21.f);
            float v = __expf(end_t[jj]);
            float logC = 0.f;
            for (int k = 3; k >= 0; k--) {
                int lo = 128 * k; if (lo < m + 1) lo = m + 1;
                int hi = 128 * k + 127; if (hi > len - 1) hi = len - 1;
                if (lo > hi) continue;
                wait_flag(&g_tflag[4 * b + k]);
                __threadfence();
                v = crf_run(v, logC, tEb, lg, jj, hi, -1, hi - lo + 1);
            }
            s_ub[lane] = v;
            if (lane == 0) s_cb = logC;
        } else {
            float num = 0.f;
            for (int k = 0; k < 4; k++) {
                int lo = 128 * k;
                int hi = 128 * k + 127; if (hi > len - 1) hi = len - 1;
                if (lo > hi) continue;
                wait_flag(&g_tflag[4 * b + k]);
                __threadfence();
                for (int t = lo + lane; t <= hi; t += 32) {
                    int lt = lab[t];
                    float e = lg[t * KK + lt];
                    num += (t == 0) ? (start_t[lt] + e)
                                    : (e + trans[lab[t - 1] * KK + lt]);
                }
            }
#pragma unroll
            for (int o = 16; o; o >>= 1)
                num += __shfl_xor_sync(FULLMASK, num, o);
            if (lane == 0) {
                s_num = num;
                s_end = end_t[lab[len - 1]];
            }
        }
    }

    __syncthreads();
    if (tid == 0) {
        g_tflag[4 * b + 0] = 0;
        g_tflag[4 * b + 1] = 0;
        g_tflag[4 * b + 2] = 0;
        g_tflag[4 * b + 3] = 0;
    }

    if (w == 0) {
        float p = (lane < KK) ? s_uf[lane] * s_ub[lane] : 0.f;
#pragma unroll
        for (int o = 16; o; o >>= 1) p += __shfl_xor_sync(FULLMASK, p, o);
        float logZ = __logf(p) + s_cf + s_cb;
        if (lane == 0) {
            g_partial[b] = logZ - (s_num + s_end);
            __threadfence();
            int old = atomicAdd(&g_ctr, 1);
            if (old == BB - 1) {
                __threadfence();
                float tot = 0.f;
                for (int i = 0; i < BB; i++) tot += g_partial[i];
                out_nll[0] = tot;
                g_ctr = 0;
            }
        }
    }
}

// ---------------------------------------------------------------------------
extern "C" void kernel_launch(void* const* d_in, const int* in_sizes, int n_in,
                              void* d_out, int out_size) {
    const float* hidden  = (const float*)d_in[0];
    const float* W       = (const float*)d_in[1];
    const float* b       = (const float*)d_in[2];
    const float* start_t = (const float*)d_in[3];
    const float* trans   = (const float*)d_in[4];
    const float* end_t   = (const float*)d_in[5];
    const int*   labels  = (const int*)d_in[6];
    const void*  mask    = (const void*)d_in[7];

    float* out     = (float*)d_out;
    float* out_nll = out + (out_size - 1);

    cudaFuncSetAttribute(fused_kernel,
                         cudaFuncAttributeMaxDynamicSharedMemorySize, GSMEM);

    fused_kernel<<<GRID, GT, GSMEM>>>(hidden, W, b, start_t, trans, end_t,
                                      labels, mask, out, out_nll);
}

// round 9
// speedup vs baseline: 1.5605x; 1.5605x over previous
#include <cuda_runtime.h>
#include <cstdint>

#define BB 64
#define SS 512
#define HH 768
#define KK 21
#define FULLMASK 0xffffffffu
#define LOG21 3.0445224377234229f

// ---------------------------------------------------------------------------
// helpers
// ---------------------------------------------------------------------------
__device__ __forceinline__ void fma2(unsigned long long& acc,
                                     unsigned long long a,
                                     unsigned long long b) {
    asm("fma.rn.f32x2 %0, %1, %2, %0;" : "+l"(acc) : "l"(a), "l"(b));
}
__device__ __forceinline__ float2 unpack2(unsigned long long v) {
    float lo, hi;
    asm("mov.b64 {%0,%1}, %2;" : "=f"(lo), "=f"(hi) : "l"(v));
    return make_float2(lo, hi);
}
__device__ __forceinline__ float rcpa(float x) {
    float r;
    asm("rcp.approx.f32 %0, %1;" : "=f"(r) : "f"(x));
    return r;
}
__device__ __forceinline__ void cpa8(void* dst, const void* src) {
    uint32_t d = (uint32_t)__cvta_generic_to_shared(dst);
    asm volatile("cp.async.ca.shared.global [%0], [%1], 8;\n" ::"r"(d), "l"(src));
}
__device__ __forceinline__ void cpa16(void* dst, const void* src) {
    uint32_t d = (uint32_t)__cvta_generic_to_shared(dst);
    asm volatile("cp.async.cg.shared.global [%0], [%1], 16;\n" ::"r"(d), "l"(src));
}

__device__ float4 g_wpack[384 * 11];
__device__ float  g_partial[BB];
__device__ int    g_ctr = 0;
__device__ int    g_packflag = 0;   // set-once: g_wpack content replay-invariant

__device__ __forceinline__ void wait_flag(volatile int* f) {
    while (*f == 0) __nanosleep(64);
}

// ---------------------------------------------------------------------------
// GEMM config: 512 tiles of 64 rows; GT=128; split-K x4; 2 rows/thread.
//   Block 0 of the launch packs W; gemm blocks are 1..512.
// ---------------------------------------------------------------------------
#define GT    128
#define GR    64
#define GSTR  66              // 64 k + 2 pad
#define WCH   352             // 32 k-pairs * 11 col-pairs per 64-k chunk
#define NCH   12
#define HFLOATS (GR * GSTR)   // 4224 floats per hidden buffer
#define GSMEM (2 * HFLOATS * 4 + 2 * WCH * 16)   // 45056 B

__global__ __launch_bounds__(GT) void gemm_kernel(
    const float* __restrict__ hidden,
    const float* __restrict__ Wg,
    const float* __restrict__ bg,
    float* __restrict__ out) {
    extern __shared__ float dsm[];
    const int tid = threadIdx.x;

    // ---------------- pack block ----------------
    if (blockIdx.x == 0) {
        for (int idx = tid; idx < 384 * 11; idx += GT) {
            int p = idx / 11, cc = idx - p * 11;
            int c0 = 2 * cc, c1 = c0 + 1;
            float a = Wg[(2 * p)     * KK + c0];
            float b = Wg[(2 * p + 1) * KK + c0];
            float c = (c1 < KK) ? Wg[(2 * p)     * KK + c1] : 0.f;
            float d = (c1 < KK) ? Wg[(2 * p + 1) * KK + c1] : 0.f;
            g_wpack[idx] = make_float4(a, b, c, d);
        }
        __threadfence();
        __syncthreads();
        if (tid == 0) atomicExch(&g_packflag, 1);
        return;
    }

    // ---------------- gemm blocks ----------------
    float*  shh = dsm;                            // [2][HFLOATS]
    float4* wb  = (float4*)(dsm + 2 * HFLOATS);   // [2][WCH]
    const int r = tid & 31;       // rows r and r+32
    const int q = tid >> 5;       // k-quarter (16 floats of the 64-k chunk)
    const size_t rowBase = (size_t)(blockIdx.x - 1) * GR;

    auto LOADH = [&](int c, int buf) {
        const float* hsrc = hidden + rowBase * HH + c * 64;
        float* dst = shh + buf * HFLOATS;
#pragma unroll
        for (int j = 0; j < 16; j++) {
            int idx = tid + j * GT;               // 2048 8B units
            int row = idx >> 5, u8 = idx & 31;
            cpa8(&dst[row * GSTR + u8 * 2], hsrc + (size_t)row * HH + u8 * 2);
        }
    };
    auto LOADW = [&](int c, int buf) {
#pragma unroll
        for (int j = 0; j < 3; j++) {
            int idx = tid + j * GT;
            if (idx < WCH) cpa16(&wb[buf * WCH + idx], &g_wpack[c * WCH + idx]);
        }
    };

    unsigned long long accA[KK], accB[KK];
#pragma unroll
    for (int i = 0; i < KK; i++) { accA[i] = 0ull; accB[i] = 0ull; }

    // prologue: hidden chunk 0 in flight while W pack completes
    LOADH(0, 0);
    asm volatile("cp.async.commit_group;\n");
    wait_flag(&g_packflag);
    __threadfence();
    LOADW(0, 0);
    asm volatile("cp.async.commit_group;\n");

    for (int c = 0; c < NCH; c++) {
        if (c + 1 < NCH) {
            LOADH(c + 1, (c + 1) & 1);
            LOADW(c + 1, (c + 1) & 1);
            asm volatile("cp.async.commit_group;\n");
            asm volatile("cp.async.wait_group 1;\n");
        } else {
            asm volatile("cp.async.wait_group 0;\n");
        }
        __syncthreads();

        const float*  hpA = &shh[(c & 1) * HFLOATS + r * GSTR + q * 16];
        const float*  hpB = hpA + 32 * GSTR;
        const float4* wp  = &wb[(c & 1) * WCH + (q * 8) * 11];
#pragma unroll
        for (int p = 0; p < 8; p++) {
            unsigned long long h2a = *(const unsigned long long*)&hpA[2 * p];
            unsigned long long h2b = *(const unsigned long long*)&hpB[2 * p];
            const ulonglong2* wrow = (const ulonglong2*)&wp[p * 11];
#pragma unroll
            for (int cc = 0; cc < 10; cc++) {
                ulonglong2 w2 = wrow[cc];
                fma2(accA[2 * cc],     h2a, w2.x);
                fma2(accA[2 * cc + 1], h2a, w2.y);
                fma2(accB[2 * cc],     h2b, w2.x);
                fma2(accB[2 * cc + 1], h2b, w2.y);
            }
            ulonglong2 w2 = wrow[10];
            fma2(accA[20], h2a, w2.x);
            fma2(accB[20], h2b, w2.x);
        }
        __syncthreads();
    }

    // epilogue: reduce pairs; combine 4 k-quarters via smem; bias; store
    float resA[KK], resB[KK];
#pragma unroll
    for (int cc = 0; cc < KK; cc++) {
        float2 fa = unpack2(accA[cc]);
        float2 fb = unpack2(accB[cc]);
        resA[cc] = fa.x + fa.y;
        resB[cc] = fb.x + fb.y;
    }
    float* bufA  = shh;                 // 64*22
    float* bufB  = shh + GR * 22;       // 64*22
    float* shOut = shh + 2 * GR * 22;   // 64*21
    if (q == 1 || q == 3) {
        float* bf = (q == 1) ? bufA : bufB;
#pragma unroll
        for (int cc = 0; cc < KK; cc++) {
            bf[r * 22 + cc] = resA[cc];
            bf[(32 + r) * 22 + cc] = resB[cc];
        }
    }
    __syncthreads();
    if (q == 0 || q == 2) {
        float* bf = (q == 0) ? bufA : bufB;
#pragma unroll
        for (int cc = 0; cc < KK; cc++) {
            resA[cc] += bf[r * 22 + cc];
            resB[cc] += bf[(32 + r) * 22 + cc];
        }
    }
    __syncthreads();
    if (q == 2) {
#pragma unroll
        for (int cc = 0; cc < KK; cc++) {
            bufA[r * 22 + cc] = resA[cc];
            bufA[(32 + r) * 22 + cc] = resB[cc];
        }
    }
    __syncthreads();
    if (q == 0) {
#pragma unroll
        for (int cc = 0; cc < KK; cc++) {
            shOut[r * KK + cc] = resA[cc] + bufA[r * 22 + cc] + bg[cc];
            shOut[(32 + r) * KK + cc] =
                resB[cc] + bufA[(32 + r) * 22 + cc] + bg[cc];
        }
    }
    __syncthreads();
    float* outp = out + rowBase * KK;
    for (int i = tid; i < GR * KK; i += GT) outp[i] = shOut[i];
}

// ---------------------------------------------------------------------------
// CRF (R5 bidirectional, unchanged) + fused final reduction
// ---------------------------------------------------------------------------
#define RN 16

__device__ __forceinline__ int seq_len_w(const void* maskraw, int b, int lane) {
    const int* im = (const int*)maskraw;
    bool bytes = (im[0] != 1);
    int len = 0;
    if (!bytes) {
        const int* m = im + b * SS;
        for (int t = lane; t < SS; t += 32) len += (m[t] != 0);
    } else {
        const unsigned char* m = (const unsigned char*)maskraw + b * SS;
        for (int t = lane; t < SS; t += 32) len += (m[t] != 0);
    }
#pragma unroll
    for (int o = 16; o; o >>= 1) len += __shfl_xor_sync(FULLMASK, len, o);
    return len;
}

__device__ __forceinline__ float crf_step(float u, const float* tE, float e0) {
    float s[7];
#pragma unroll
    for (int i = 0; i < 7; i++) {
        float u0 = __shfl_sync(FULLMASK, u, 3 * i);
        float u1 = __shfl_sync(FULLMASK, u, 3 * i + 1);
        float u2 = __shfl_sync(FULLMASK, u, 3 * i + 2);
        float p = u0 * tE[3 * i];
        p = fmaf(u1, tE[3 * i + 1], p);
        p = fmaf(u2, tE[3 * i + 2], p);
        s[i] = p;
    }
    return (((s[0] + s[1]) + (s[2] + s[3])) + ((s[4] + s[5]) + s[6])) * e0;
}

__device__ __forceinline__ float crf_run(float u, float& logC, const float* tE,
                                         const float* lg, int jj,
                                         int base, int dir, int n) {
    if (n <= 0) return u;
    float ev[RN], evn[RN];
#pragma unroll
    for (int j = 0; j < RN; j++) {
        int idx = (j < n) ? j : n - 1;
        ev[j] = lg[(base + dir * idx) * KK + jj];
    }
    int pos = 0;
    while (pos + RN <= n) {
#pragma unroll
        for (int j = 0; j < RN; j++) {
            int idx = pos + RN + j; idx = (idx < n) ? idx : n - 1;
            evn[j] = lg[(base + dir * idx) * KK + jj];
        }
        float e0 = __expf(ev[0]);
#pragma unroll
        for (int j = 0; j < RN; j++) {
            float e1 = __expf(ev[(j + 1) & (RN - 1)]);
            u = crf_step(u, tE, e0);
            e0 = e1;
        }
        float c = __shfl_sync(FULLMASK, u, 0);
        u *= rcpa(c);
        logC += __logf(c);
#pragma unroll
        for (int j = 0; j < RN; j++) ev[j] = evn[j];
        pos += RN;
    }
    int tail = n - pos;
    for (int j = 0; j < tail; j++) {
        float e0 = __expf(ev[j]);
        u = crf_step(u, tE, e0);
    }
    if (tail) {
        float c = __shfl_sync(FULLMASK, u, 0);
        u *= rcpa(c);
        logC += __logf(c);
    }
    logC += (float)n * LOG21;
    return u;
}

__global__ __launch_bounds__(96) void crf_kernel(
    const float* __restrict__ logits,
    const int*   __restrict__ labels,
    const void*  __restrict__ maskraw,
    const float* __restrict__ start_t,
    const float* __restrict__ trans,
    const float* __restrict__ end_t,
    float* __restrict__ out_nll) {
    const int b = blockIdx.x;
    const int tid = threadIdx.x;
    const int lane = tid & 31;
    const int w = tid >> 5;
    const int jj = (lane < KK) ? lane : KK - 1;

    __shared__ float s_uf[32], s_ub[32];
    __shared__ float s_cf, s_cb, s_num, s_end;

    const int len = seq_len_w(maskraw, b, lane);
    const int m = len >> 1;
    const int*   lab = labels + b * SS;
    const float* lg  = logits + (size_t)b * SS * KK;

    if (w == 2) {
        float num = 0.f;
        for (int t = lane; t < len; t += 32) {
            int lt = lab[t];
            float e = lg[t * KK + lt];
            num += (t == 0) ? (start_t[lt] + e)
                            : (e + trans[lab[t - 1] * KK + lt]);
        }
#pragma unroll
        for (int o = 16; o; o >>= 1) num += __shfl_xor_sync(FULLMASK, num, o);
        if (lane == 0) {
            s_num = num;
            s_end = end_t[lab[len - 1]];
        }
    } else if (w == 0) {
        float tE[KK];
#pragma unroll
        for (int i = 0; i < KK; i++)
            tE[i] = __expf(trans[i * KK + jj]) * (1.f / 21.f);
        float a0 = (lane < KK) ? (start_t[lane] + lg[lane]) : -1e30f;
        float m0 = a0;
#pragma unroll
        for (int o = 16; o; o >>= 1)
            m0 = fmaxf(m0, __shfl_xor_sync(FULLMASK, m0, o));
        float u = __expf(a0 - m0);
        float logC = m0;
        u = crf_run(u, logC, tE, lg, jj, 1, +1, m);
        s_uf[lane] = u;
        if (lane == 0) s_cf = logC;
    } else {
        float tEb[KK];
#pragma unroll
        for (int i = 0; i < KK; i++)
            tEb[i] = __expf(trans[jj * KK + i]) * (1.f / 21.f);
        float v = __expf(end_t[jj]);
        float logC = 0.f;
        v = crf_run(v, logC, tEb, lg, jj, len - 1, -1, len - 1 - m);
        s_ub[lane] = v;
        if (lane == 0) s_cb = logC;
    }

    __syncthreads();

    if (w == 0) {
        float p = (lane < KK) ? s_uf[lane] * s_ub[lane] : 0.f;
#pragma unroll
        for (int o = 16; o; o >>= 1) p += __shfl_xor_sync(FULLMASK, p, o);
        float logZ = __logf(p) + s_cf + s_cb;
        if (lane == 0) {
            g_partial[b] = logZ - (s_num + s_end);
            __threadfence();
            int old = atomicAdd(&g_ctr, 1);
            if (old == BB - 1) {
                __threadfence();
                float tot = 0.f;
                for (int i = 0; i < BB; i++) tot += g_partial[i];
                out_nll[0] = tot;
                g_ctr = 0;
            }
        }
    }
}

// ---------------------------------------------------------------------------
extern "C" void kernel_launch(void* const* d_in, const int* in_sizes, int n_in,
                              void* d_out, int out_size) {
    const float* hidden  = (const float*)d_in[0];
    const float* W       = (const float*)d_in[1];
    const float* b       = (const float*)d_in[2];
    const float* start_t = (const float*)d_in[3];
    const float* trans   = (const float*)d_in[4];
    const float* end_t   = (const float*)d_in[5];
    const int*   labels  = (const int*)d_in[6];
    const void*  mask    = (const void*)d_in[7];

    float* out     = (float*)d_out;
    float* out_nll = out + (out_size - 1);

    cudaFuncSetAttribute(gemm_kernel,
                         cudaFuncAttributeMaxDynamicSharedMemorySize, GSMEM);

    gemm_kernel<<<1 + (BB * SS) / GR, GT, GSMEM>>>(hidden, W, b, out);
    crf_kernel<<<BB, 96>>>(out, labels, mask, start_t, trans, end_t, out_nll);
}

// round 10
// speedup vs baseline: 1.8305x; 1.1730x over previous
#include <cuda_runtime.h>
#include <cstdint>

#define BB 64
#define SS 512
#define HH 768
#define KK 21
#define FULLMASK 0xffffffffu
#define LOG21 3.0445224377234229f

// ---------------------------------------------------------------------------
// helpers
// ---------------------------------------------------------------------------
__device__ __forceinline__ void fma2(unsigned long long& acc,
                                     unsigned long long a,
                                     unsigned long long b) {
    asm("fma.rn.f32x2 %0, %1, %2, %0;" : "+l"(acc) : "l"(a), "l"(b));
}
__device__ __forceinline__ float2 unpack2(unsigned long long v) {
    float lo, hi;
    asm("mov.b64 {%0,%1}, %2;" : "=f"(lo), "=f"(hi) : "l"(v));
    return make_float2(lo, hi);
}
__device__ __forceinline__ float rcpa(float x) {
    float r;
    asm("rcp.approx.f32 %0, %1;" : "=f"(r) : "f"(x));
    return r;
}
__device__ __forceinline__ void cpa8(void* dst, const void* src) {
    uint32_t d = (uint32_t)__cvta_generic_to_shared(dst);
    asm volatile("cp.async.ca.shared.global [%0], [%1], 8;\n" ::"r"(d), "l"(src));
}
__device__ __forceinline__ void cpa16(void* dst, const void* src) {
    uint32_t d = (uint32_t)__cvta_generic_to_shared(dst);
    asm volatile("cp.async.cg.shared.global [%0], [%1], 16;\n" ::"r"(d), "l"(src));
}

__device__ float4 g_wpack[384 * 11];
__device__ float  g_partial[BB];
__device__ int    g_ctr = 0;
__device__ int    g_packflag = 0;   // set-once: g_wpack content replay-invariant

__device__ __forceinline__ void wait_flag(volatile int* f) {
    while (*f == 0) __nanosleep(64);
}

// ---------------------------------------------------------------------------
// GEMM (identical to R9): 512 tiles of 64 rows; GT=128; split-K x4;
//   2 rows/thread; block 0 packs W.
// ---------------------------------------------------------------------------
#define GT    128
#define GR    64
#define GSTR  66
#define WCH   352
#define NCH   12
#define HFLOATS (GR * GSTR)
#define GSMEM (2 * HFLOATS * 4 + 2 * WCH * 16)

__global__ __launch_bounds__(GT) void gemm_kernel(
    const float* __restrict__ hidden,
    const float* __restrict__ Wg,
    const float* __restrict__ bg,
    float* __restrict__ out) {
    extern __shared__ float dsm[];
    const int tid = threadIdx.x;

    if (blockIdx.x == 0) {
        for (int idx = tid; idx < 384 * 11; idx += GT) {
            int p = idx / 11, cc = idx - p * 11;
            int c0 = 2 * cc, c1 = c0 + 1;
            float a = Wg[(2 * p)     * KK + c0];
            float b = Wg[(2 * p + 1) * KK + c0];
            float c = (c1 < KK) ? Wg[(2 * p)     * KK + c1] : 0.f;
            float d = (c1 < KK) ? Wg[(2 * p + 1) * KK + c1] : 0.f;
            g_wpack[idx] = make_float4(a, b, c, d);
        }
        __threadfence();
        __syncthreads();
        if (tid == 0) atomicExch(&g_packflag, 1);
        return;
    }

    float*  shh = dsm;
    float4* wb  = (float4*)(dsm + 2 * HFLOATS);
    const int r = tid & 31;
    const int q = tid >> 5;
    const size_t rowBase = (size_t)(blockIdx.x - 1) * GR;

    auto LOADH = [&](int c, int buf) {
        const float* hsrc = hidden + rowBase * HH + c * 64;
        float* dst = shh + buf * HFLOATS;
#pragma unroll
        for (int j = 0; j < 16; j++) {
            int idx = tid + j * GT;
            int row = idx >> 5, u8 = idx & 31;
            cpa8(&dst[row * GSTR + u8 * 2], hsrc + (size_t)row * HH + u8 * 2);
        }
    };
    auto LOADW = [&](int c, int buf) {
#pragma unroll
        for (int j = 0; j < 3; j++) {
            int idx = tid + j * GT;
            if (idx < WCH) cpa16(&wb[buf * WCH + idx], &g_wpack[c * WCH + idx]);
        }
    };

    unsigned long long accA[KK], accB[KK];
#pragma unroll
    for (int i = 0; i < KK; i++) { accA[i] = 0ull; accB[i] = 0ull; }

    LOADH(0, 0);
    asm volatile("cp.async.commit_group;\n");
    wait_flag(&g_packflag);
    __threadfence();
    LOADW(0, 0);
    asm volatile("cp.async.commit_group;\n");

    for (int c = 0; c < NCH; c++) {
        if (c + 1 < NCH) {
            LOADH(c + 1, (c + 1) & 1);
            LOADW(c + 1, (c + 1) & 1);
            asm volatile("cp.async.commit_group;\n");
            asm volatile("cp.async.wait_group 1;\n");
        } else {
            asm volatile("cp.async.wait_group 0;\n");
        }
        __syncthreads();

        const float*  hpA = &shh[(c & 1) * HFLOATS + r * GSTR + q * 16];
        const float*  hpB = hpA + 32 * GSTR;
        const float4* wp  = &wb[(c & 1) * WCH + (q * 8) * 11];
#pragma unroll
        for (int p = 0; p < 8; p++) {
            unsigned long long h2a = *(const unsigned long long*)&hpA[2 * p];
            unsigned long long h2b = *(const unsigned long long*)&hpB[2 * p];
            const ulonglong2* wrow = (const ulonglong2*)&wp[p * 11];
#pragma unroll
            for (int cc = 0; cc < 10; cc++) {
                ulonglong2 w2 = wrow[cc];
                fma2(accA[2 * cc],     h2a, w2.x);
                fma2(accA[2 * cc + 1], h2a, w2.y);
                fma2(accB[2 * cc],     h2b, w2.x);
                fma2(accB[2 * cc + 1], h2b, w2.y);
            }
            ulonglong2 w2 = wrow[10];
            fma2(accA[20], h2a, w2.x);
            fma2(accB[20], h2b, w2.x);
        }
        __syncthreads();
    }

    float resA[KK], resB[KK];
#pragma unroll
    for (int cc = 0; cc < KK; cc++) {
        float2 fa = unpack2(accA[cc]);
        float2 fb = unpack2(accB[cc]);
        resA[cc] = fa.x + fa.y;
        resB[cc] = fb.x + fb.y;
    }
    float* bufA  = shh;
    float* bufB  = shh + GR * 22;
    float* shOut = shh + 2 * GR * 22;
    if (q == 1 || q == 3) {
        float* bf = (q == 1) ? bufA : bufB;
#pragma unroll
        for (int cc = 0; cc < KK; cc++) {
            bf[r * 22 + cc] = resA[cc];
            bf[(32 + r) * 22 + cc] = resB[cc];
        }
    }
    __syncthreads();
    if (q == 0 || q == 2) {
        float* bf = (q == 0) ? bufA : bufB;
#pragma unroll
        for (int cc = 0; cc < KK; cc++) {
            resA[cc] += bf[r * 22 + cc];
            resB[cc] += bf[(32 + r) * 22 + cc];
        }
    }
    __syncthreads();
    if (q == 2) {
#pragma unroll
        for (int cc = 0; cc < KK; cc++) {
            bufA[r * 22 + cc] = resA[cc];
            bufA[(32 + r) * 22 + cc] = resB[cc];
        }
    }
    __syncthreads();
    if (q == 0) {
#pragma unroll
        for (int cc = 0; cc < KK; cc++) {
            shOut[r * KK + cc] = resA[cc] + bufA[r * 22 + cc] + bg[cc];
            shOut[(32 + r) * KK + cc] =
                resB[cc] + bufA[(32 + r) * 22 + cc] + bg[cc];
        }
    }
    __syncthreads();
    float* outp = out + rowBase * KK;
    for (int i = tid; i < GR * KK; i += GT) outp[i] = shOut[i];
}

// ---------------------------------------------------------------------------
// CRF: bidirectional, state in warp-private smem double buffer.
//   Step: 6x LDS.128 broadcast + padded 24-dot + 1 STS + 1 __syncwarp.
//   Renorm folded into next group's first emission factor (nearly free).
// ---------------------------------------------------------------------------
#define RN 16

__device__ __forceinline__ int seq_len_w(const void* maskraw, int b, int lane) {
    const int* im = (const int*)maskraw;
    bool bytes = (im[0] != 1);
    int len = 0;
    if (!bytes) {
        const int* m = im + b * SS;
        for (int t = lane; t < SS; t += 32) len += (m[t] != 0);
    } else {
        const unsigned char* m = (const unsigned char*)maskraw + b * SS;
        for (int t = lane; t < SS; t += 32) len += (m[t] != 0);
    }
#pragma unroll
    for (int o = 16; o; o >>= 1) len += __shfl_xor_sync(FULLMASK, len, o);
    return len;
}

// one step: read full state (broadcast LDS.128), dot with own tE column,
// scale by e0, store own component to the other buffer, syncwarp.
__device__ __forceinline__ float crf_sstep(float* sb, int rb, const float* tE,
                                           float e0, int lane) {
    const float4* sp = (const float4*)(sb + rb * 24);
    float4 v0 = sp[0], v1 = sp[1], v2 = sp[2], v3 = sp[3], v4 = sp[4], v5 = sp[5];
    float a0 = v0.x * tE[0];
    a0 = fmaf(v0.y, tE[1], a0); a0 = fmaf(v0.z, tE[2], a0); a0 = fmaf(v0.w, tE[3], a0);
    float a1 = v1.x * tE[4];
    a1 = fmaf(v1.y, tE[5], a1); a1 = fmaf(v1.z, tE[6], a1); a1 = fmaf(v1.w, tE[7], a1);
    float a2 = v2.x * tE[8];
    a2 = fmaf(v2.y, tE[9], a2); a2 = fmaf(v2.z, tE[10], a2); a2 = fmaf(v2.w, tE[11], a2);
    float a3 = v3.x * tE[12];
    a3 = fmaf(v3.y, tE[13], a3); a3 = fmaf(v3.z, tE[14], a3); a3 = fmaf(v3.w, tE[15], a3);
    float a4 = v4.x * tE[16];
    a4 = fmaf(v4.y, tE[17], a4); a4 = fmaf(v4.z, tE[18], a4); a4 = fmaf(v4.w, tE[19], a4);
    float a5 = v5.x * tE[20];           // tE[21..23]=0, pad state = 0
    float y = ((a0 + a1) + (a2 + a3)) + (a4 + a5);
    float u = y * e0;
    if (lane < KK) sb[(rb ^ 1) * 24 + lane] = u;
    __syncwarp();
    return u;
}

// n steps; emission t-index = base + dir*stepIdx. sb = warp-private [2][24].
__device__ __forceinline__ float crf_run_s(float uinit, float& logC,
                                           const float* tE, float* sb,
                                           const float* lg, int jj,
                                           int base, int dir, int n, int lane) {
    if (lane < 24) {
        sb[lane]      = (lane < KK) ? uinit : 0.f;
        sb[24 + lane] = 0.f;
    }
    __syncwarp();
    if (n <= 0) return uinit;

    float u = uinit;
    float ev[RN], evn[RN];
#pragma unroll
    for (int j = 0; j < RN; j++) {
        int idx = (j < n) ? j : n - 1;
        ev[j] = lg[(base + dir * idx) * KK + jj];
    }
    float pend = 1.f, lpend = 0.f;
    int rb = 0;
    int pos = 0;
    while (pos + RN <= n) {
#pragma unroll
        for (int j = 0; j < RN; j++) {               // prefetch next group
            int idx = pos + RN + j; idx = (idx < n) ? idx : n - 1;
            evn[j] = lg[(base + dir * idx) * KK + jj];
        }
        float e0 = __expf(ev[0]) * pend;             // fold prior renorm
        logC += lpend;
#pragma unroll
        for (int j = 0; j < RN; j++) {
            float e1 = __expf(ev[(j + 1) & (RN - 1)]);
            u = crf_sstep(sb, rb, tE, e0, lane);
            rb ^= 1;
            e0 = e1;
        }
        float c = sb[rb * 24];                       // rb back to 0 (RN even)
        pend = rcpa(c);
        lpend = __logf(c);
#pragma unroll
        for (int j = 0; j < RN; j++) ev[j] = evn[j];
        pos += RN;
    }
    int tail = n - pos;
    if (tail) {
        float e0 = __expf(ev[0]) * pend;
        logC += lpend;
        for (int j = 0; j < tail; j++) {
            u = crf_sstep(sb, rb, tE, e0, lane);
            rb ^= 1;
            e0 = __expf(ev[(j + 1) & (RN - 1)]);
        }
    }
    logC += (float)n * LOG21;
    return u;                                        // own component (lane<KK)
}

__global__ __launch_bounds__(96) void crf_kernel(
    const float* __restrict__ logits,
    const int*   __restrict__ labels,
    const void*  __restrict__ maskraw,
    const float* __restrict__ start_t,
    const float* __restrict__ trans,
    const float* __restrict__ end_t,
    float* __restrict__ out_nll) {
    const int b = blockIdx.x;
    const int tid = threadIdx.x;
    const int lane = tid & 31;
    const int w = tid >> 5;
    const int jj = (lane < KK) ? lane : KK - 1;

    __shared__ __align__(16) float s_st[2][2 * 24];  // warps 0,1 state buffers
    __shared__ float s_uf[32], s_ub[32];
    __shared__ float s_cf, s_cb, s_num, s_end;

    const int len = seq_len_w(maskraw, b, lane);
    const int m = len >> 1;
    const int*   lab = labels + b * SS;
    const float* lg  = logits + (size_t)b * SS * KK;

    if (w == 2) {
        float num = 0.f;
        for (int t = lane; t < len; t += 32) {
            int lt = lab[t];
            float e = lg[t * KK + lt];
            num += (t == 0) ? (start_t[lt] + e)
                            : (e + trans[lab[t - 1] * KK + lt]);
        }
#pragma unroll
        for (int o = 16; o; o >>= 1) num += __shfl_xor_sync(FULLMASK, num, o);
        if (lane == 0) {
            s_num = num;
            s_end = end_t[lab[len - 1]];
        }
    } else if (w == 0) {
        float tE[24];
#pragma unroll
        for (int i = 0; i < KK; i++)
            tE[i] = __expf(trans[i * KK + jj]) * (1.f / 21.f);
        tE[21] = tE[22] = tE[23] = 0.f;
        float a0 = (lane < KK) ? (start_t[lane] + lg[lane]) : -1e30f;
        float m0 = a0;
#pragma unroll
        for (int o = 16; o; o >>= 1)
            m0 = fmaxf(m0, __shfl_xor_sync(FULLMASK, m0, o));
        float u = __expf(a0 - m0);
        float logC = m0;
        u = crf_run_s(u, logC, tE, s_st[0], lg, jj, 1, +1, m, lane);
        s_uf[lane] = u;
        if (lane == 0) s_cf = logC;
    } else {
        float tEb[24];
#pragma unroll
        for (int i = 0; i < KK; i++)
            tEb[i] = __expf(trans[jj * KK + i]) * (1.f / 21.f);
        tEb[21] = tEb[22] = tEb[23] = 0.f;
        float v = __expf(end_t[jj]);
        float logC = 0.f;
        v = crf_run_s(v, logC, tEb, s_st[1], lg, jj, len - 1, -1,
                      len - 1 - m, lane);
        s_ub[lane] = v;
        if (lane == 0) s_cb = logC;
    }

    __syncthreads();

    if (w == 0) {
        float p = (lane < KK) ? s_uf[lane] * s_ub[lane] : 0.f;
#pragma unroll
        for (int o = 16; o; o >>= 1) p += __shfl_xor_sync(FULLMASK, p, o);
        float logZ = __logf(p) + s_cf + s_cb;
        if (lane == 0) {
            g_partial[b] = logZ - (s_num + s_end);
            __threadfence();
            int old = atomicAdd(&g_ctr, 1);
            if (old == BB - 1) {
                __threadfence();
                float tot = 0.f;
                for (int i = 0; i < BB; i++) tot += g_partial[i];
                out_nll[0] = tot;
                g_ctr = 0;
            }
        }
    }
}

// ---------------------------------------------------------------------------
extern "C" void kernel_launch(void* const* d_in, const int* in_sizes, int n_in,
                              void* d_out, int out_size) {
    const float* hidden  = (const float*)d_in[0];
    const float* W       = (const float*)d_in[1];
    const float* b       = (const float*)d_in[2];
    const float* start_t = (const float*)d_in[3];
    const float* trans   = (const float*)d_in[4];
    const float* end_t   = (const float*)d_in[5];
    const int*   labels  = (const int*)d_in[6];
    const void*  mask    = (const void*)d_in[7];

    float* out     = (float*)d_out;
    float* out_nll = out + (out_size - 1);

    cudaFuncSetAttribute(gemm_kernel,
                         cudaFuncAttributeMaxDynamicSharedMemorySize, GSMEM);

    gemm_kernel<<<1 + (BB * SS) / GR, GT, GSMEM>>>(hidden, W, b, out);
    crf_kernel<<<BB, 96>>>(out, labels, mask, start_t, trans, end_t, out_nll);
}